// round 1
// baseline (speedup 1.0000x reference)
#include <cuda_runtime.h>
#include <math.h>

// Problem constants
#define BB   2
#define SS   2048
#define HH   2048
#define NHH  16
#define HDD  128
#define SCALE 0.08838834764831845f   // 1/sqrt(128)

// Scratch (device globals: allocation-guard-safe)
__device__ float g_q[(size_t)BB * NHH * SS * HDD];    // [B,NH,S,HD]
__device__ float g_k[(size_t)BB * NHH * SS * HDD];
__device__ float g_v[(size_t)BB * NHH * SS * HDD];
__device__ float g_ctx[(size_t)BB * SS * HH];         // [B,S,H]

// ---------------------------------------------------------------------------
// SGEMM: C[M,N] = A[M,K] * W[N,K]^T + bias[N]
// BM=BN=128, BK=16, 256 threads, 8x8 micro-tile per thread.
// MODE 0: A = x, scatter outputs to g_q/g_k/g_v in [B,NH,S,HD] layout.
// MODE 1: A = g_ctx (param ignored), write C (+bias) to `C` row-major.
// ---------------------------------------------------------------------------
template <int MODE>
__global__ __launch_bounds__(256)
void sgemm_kernel(const float* __restrict__ A,
                  const float* __restrict__ W,
                  const float* __restrict__ bias,
                  float* __restrict__ C,
                  int M, int N, int K)
{
    constexpr int BM = 128, BN = 128, BK = 16;
    __shared__ float As[BK][BM + 4];
    __shared__ float Bs[BK][BN + 4];

    const float* Ap = (MODE == 1) ? (const float*)g_ctx : A;

    const int tid = threadIdx.x;
    const int tx = tid & 15;        // 0..15 (N direction)
    const int ty = tid >> 4;        // 0..15 (M direction)
    const int m0 = blockIdx.y * BM;
    const int n0 = blockIdx.x * BN;

    float acc[8][8];
#pragma unroll
    for (int i = 0; i < 8; i++)
#pragma unroll
        for (int j = 0; j < 8; j++) acc[i][j] = 0.0f;

    for (int k0 = 0; k0 < K; k0 += BK) {
        // Load A and W tiles (transposed into smem: [k][m] / [k][n])
#pragma unroll
        for (int it = 0; it < 2; it++) {
            int vec = tid + it * 256;      // 0..511
            int r   = vec >> 2;            // 0..127
            int kk  = (vec & 3) << 2;      // 0,4,8,12
            float4 va = *(const float4*)(Ap + (size_t)(m0 + r) * K + k0 + kk);
            As[kk + 0][r] = va.x; As[kk + 1][r] = va.y;
            As[kk + 2][r] = va.z; As[kk + 3][r] = va.w;
            float4 vb = *(const float4*)(W + (size_t)(n0 + r) * K + k0 + kk);
            Bs[kk + 0][r] = vb.x; Bs[kk + 1][r] = vb.y;
            Bs[kk + 2][r] = vb.z; Bs[kk + 3][r] = vb.w;
        }
        __syncthreads();

#pragma unroll
        for (int k = 0; k < BK; k++) {
            float4 a0 = *(const float4*)&As[k][ty * 8];
            float4 a1 = *(const float4*)&As[k][ty * 8 + 4];
            float4 b0 = *(const float4*)&Bs[k][tx * 8];
            float4 b1 = *(const float4*)&Bs[k][tx * 8 + 4];
            float ar[8] = {a0.x, a0.y, a0.z, a0.w, a1.x, a1.y, a1.z, a1.w};
            float br[8] = {b0.x, b0.y, b0.z, b0.w, b1.x, b1.y, b1.z, b1.w};
#pragma unroll
            for (int i = 0; i < 8; i++)
#pragma unroll
                for (int j = 0; j < 8; j++)
                    acc[i][j] = fmaf(ar[i], br[j], acc[i][j]);
        }
        __syncthreads();
    }

    // Epilogue
    if (MODE == 0) {
#pragma unroll
        for (int i = 0; i < 8; i++) {
            int m  = m0 + ty * 8 + i;
            int bb = m >> 11;          // batch
            int s  = m & 2047;         // sequence
#pragma unroll
            for (int jv = 0; jv < 2; jv++) {
                int n     = n0 + tx * 8 + jv * 4;
                int which = n >> 11;                 // 0=q,1=k,2=v
                int rest  = n & 2047;
                int h     = rest >> 7;
                int d     = rest & 127;
                float* dst = (which == 0) ? g_q : (which == 1) ? g_k : g_v;
                float4 v;
                v.x = acc[i][jv * 4 + 0] + bias[n + 0];
                v.y = acc[i][jv * 4 + 1] + bias[n + 1];
                v.z = acc[i][jv * 4 + 2] + bias[n + 2];
                v.w = acc[i][jv * 4 + 3] + bias[n + 3];
                *(float4*)(dst + (((size_t)(bb * NHH + h)) * SS + s) * HDD + d) = v;
            }
        }
    } else {
#pragma unroll
        for (int i = 0; i < 8; i++) {
            int m = m0 + ty * 8 + i;
#pragma unroll
            for (int jv = 0; jv < 2; jv++) {
                int n = n0 + tx * 8 + jv * 4;
                float4 v;
                v.x = acc[i][jv * 4 + 0] + bias[n + 0];
                v.y = acc[i][jv * 4 + 1] + bias[n + 1];
                v.z = acc[i][jv * 4 + 2] + bias[n + 2];
                v.w = acc[i][jv * 4 + 3] + bias[n + 3];
                *(float4*)(C + (size_t)m * N + n) = v;
            }
        }
    }
}

// ---------------------------------------------------------------------------
// Causal flash attention, fp32.
// One CTA = 128 queries of one (b,h). Iterates key tiles of 128 (only kt<=qt).
// Smem: Qt[d][r] (persistent, d-major), Kt d-chunked [32][128], P row-major,
// V natural j-chunked [32][128]. 256 threads, 8x8 micro-tiles.
// ---------------------------------------------------------------------------
#define FLASH_SMEM_FLOATS (128*132 + 32*132 + 128*132 + 32*132)
#define FLASH_SMEM_BYTES  (FLASH_SMEM_FLOATS * 4)

__global__ __launch_bounds__(256)
void flash_kernel()
{
    extern __shared__ float sm[];
    float* Qt = sm;                      // [128 d][132] (r index)
    float* Kt = Qt + 128 * 132;          // [32 d][132]  (c index)
    float* Ps = Kt + 32 * 132;           // [128 r][132] (j index)
    float* Vs = Ps + 128 * 132;          // [32 j][132]  (d index)

    const int tid = threadIdx.x;
    const int tx = tid & 15;             // key/value columns
    const int ty = tid >> 4;             // query rows
    const int qt = blockIdx.x;           // query tile (0..15)
    const int bh = blockIdx.y;           // head (0..31)

    const float* Q  = g_q + (size_t)bh * SS * HDD;
    const float* Kp = g_k + (size_t)bh * SS * HDD;
    const float* Vp = g_v + (size_t)bh * SS * HDD;

    // Load Q tile transposed: Qt[d][r]
#pragma unroll
    for (int it = 0; it < 16; it++) {
        int vec = tid + it * 256;        // 0..4095
        int d4  = vec & 31;
        int r   = vec >> 5;
        float4 v = *(const float4*)(Q + ((size_t)qt * 128 + r) * HDD + d4 * 4);
        Qt[(d4 * 4 + 0) * 132 + r] = v.x;
        Qt[(d4 * 4 + 1) * 132 + r] = v.y;
        Qt[(d4 * 4 + 2) * 132 + r] = v.z;
        Qt[(d4 * 4 + 3) * 132 + r] = v.w;
    }

    float m_i[8], l_i[8], O[8][8];
#pragma unroll
    for (int i = 0; i < 8; i++) {
        m_i[i] = -1e30f;
        l_i[i] = 0.0f;
#pragma unroll
        for (int j = 0; j < 8; j++) O[i][j] = 0.0f;
    }
    __syncthreads();

    for (int kt = 0; kt <= qt; kt++) {
        float Sv[8][8];
#pragma unroll
        for (int i = 0; i < 8; i++)
#pragma unroll
            for (int j = 0; j < 8; j++) Sv[i][j] = 0.0f;

        // S = Q K^T, d-chunked
        for (int dc = 0; dc < 4; dc++) {
#pragma unroll
            for (int it = 0; it < 4; it++) {
                int vec = tid + it * 256;      // 0..1023
                int d4  = vec & 7;             // 0..7  -> d within chunk
                int c   = vec >> 3;            // 0..127
                float4 v = *(const float4*)(Kp + ((size_t)kt * 128 + c) * HDD + dc * 32 + d4 * 4);
                Kt[(d4 * 4 + 0) * 132 + c] = v.x;
                Kt[(d4 * 4 + 1) * 132 + c] = v.y;
                Kt[(d4 * 4 + 2) * 132 + c] = v.z;
                Kt[(d4 * 4 + 3) * 132 + c] = v.w;
            }
            __syncthreads();
#pragma unroll
            for (int dl = 0; dl < 32; dl++) {
                int d = dc * 32 + dl;
                float4 q0 = *(const float4*)&Qt[d * 132 + ty * 8];
                float4 q1 = *(const float4*)&Qt[d * 132 + ty * 8 + 4];
                float4 k0 = *(const float4*)&Kt[dl * 132 + tx * 8];
                float4 k1 = *(const float4*)&Kt[dl * 132 + tx * 8 + 4];
                float qr[8] = {q0.x, q0.y, q0.z, q0.w, q1.x, q1.y, q1.z, q1.w};
                float kr[8] = {k0.x, k0.y, k0.z, k0.w, k1.x, k1.y, k1.z, k1.w};
#pragma unroll
                for (int i = 0; i < 8; i++)
#pragma unroll
                    for (int j = 0; j < 8; j++)
                        Sv[i][j] = fmaf(qr[i], kr[j], Sv[i][j]);
            }
            __syncthreads();
        }

        // scale + causal mask (diagonal tile only)
        const bool diag = (kt == qt);
#pragma unroll
        for (int i = 0; i < 8; i++)
#pragma unroll
            for (int j = 0; j < 8; j++) {
                float s = Sv[i][j] * SCALE;
                if (diag && (tx * 8 + j) > (ty * 8 + i)) s = -1e30f;
                Sv[i][j] = s;
            }

        // online softmax update (row group = 16 lanes sharing ty)
#pragma unroll
        for (int i = 0; i < 8; i++) {
            float mx = Sv[i][0];
#pragma unroll
            for (int j = 1; j < 8; j++) mx = fmaxf(mx, Sv[i][j]);
            mx = fmaxf(mx, __shfl_xor_sync(0xffffffffu, mx, 8));
            mx = fmaxf(mx, __shfl_xor_sync(0xffffffffu, mx, 4));
            mx = fmaxf(mx, __shfl_xor_sync(0xffffffffu, mx, 2));
            mx = fmaxf(mx, __shfl_xor_sync(0xffffffffu, mx, 1));
            float mnew = fmaxf(m_i[i], mx);
            float corr = __expf(m_i[i] - mnew);
            m_i[i] = mnew;
            l_i[i] *= corr;
#pragma unroll
            for (int j = 0; j < 8; j++) O[i][j] *= corr;
            float rs = 0.0f;
#pragma unroll
            for (int j = 0; j < 8; j++) {
                float p = __expf(Sv[i][j] - mnew);
                Sv[i][j] = p;
                rs += p;
            }
            rs += __shfl_xor_sync(0xffffffffu, rs, 8);
            rs += __shfl_xor_sync(0xffffffffu, rs, 4);
            rs += __shfl_xor_sync(0xffffffffu, rs, 2);
            rs += __shfl_xor_sync(0xffffffffu, rs, 1);
            l_i[i] += rs;
        }

        // write P row-major (conflict-free float4 stores)
#pragma unroll
        for (int i = 0; i < 8; i++) {
            *(float4*)&Ps[(ty * 8 + i) * 132 + tx * 8] =
                make_float4(Sv[i][0], Sv[i][1], Sv[i][2], Sv[i][3]);
            *(float4*)&Ps[(ty * 8 + i) * 132 + tx * 8 + 4] =
                make_float4(Sv[i][4], Sv[i][5], Sv[i][6], Sv[i][7]);
        }

        // O += P V, j-chunked
        for (int jc = 0; jc < 4; jc++) {
#pragma unroll
            for (int it = 0; it < 4; it++) {
                int vec = tid + it * 256;      // 0..1023
                int d4  = vec & 31;
                int jl  = vec >> 5;            // 0..31
                *(float4*)&Vs[jl * 132 + d4 * 4] =
                    *(const float4*)(Vp + ((size_t)kt * 128 + jc * 32 + jl) * HDD + d4 * 4);
            }
            __syncthreads();
#pragma unroll
            for (int jl = 0; jl < 32; jl++) {
                int j = jc * 32 + jl;
                float pr[8];
#pragma unroll
                for (int i = 0; i < 8; i++) pr[i] = Ps[(ty * 8 + i) * 132 + j];
                float4 v0 = *(const float4*)&Vs[jl * 132 + tx * 8];
                float4 v1 = *(const float4*)&Vs[jl * 132 + tx * 8 + 4];
                float vr[8] = {v0.x, v0.y, v0.z, v0.w, v1.x, v1.y, v1.z, v1.w};
#pragma unroll
                for (int i = 0; i < 8; i++)
#pragma unroll
                    for (int jj = 0; jj < 8; jj++)
                        O[i][jj] = fmaf(pr[i], vr[jj], O[i][jj]);
            }
            __syncthreads();
        }
    }

    // Finalize and write ctx[b][s][h*128+d]
    const int b = bh >> 4, h = bh & 15;
#pragma unroll
    for (int i = 0; i < 8; i++) {
        float inv = 1.0f / l_i[i];
        int s = qt * 128 + ty * 8 + i;
        float* dst = g_ctx + ((size_t)b * SS + s) * HH + h * HDD + tx * 8;
        *(float4*)(dst)     = make_float4(O[i][0] * inv, O[i][1] * inv,
                                          O[i][2] * inv, O[i][3] * inv);
        *(float4*)(dst + 4) = make_float4(O[i][4] * inv, O[i][5] * inv,
                                          O[i][6] * inv, O[i][7] * inv);
    }
}

// ---------------------------------------------------------------------------
// Launch: qkv GEMM -> flash attention -> out GEMM (default stream, capturable)
// ---------------------------------------------------------------------------
extern "C" void kernel_launch(void* const* d_in, const int* in_sizes, int n_in,
                              void* d_out, int out_size)
{
    (void)in_sizes; (void)n_in; (void)out_size;
    const float* x     = (const float*)d_in[0];
    // d_in[1] = attn_mask (known causal tril; handled analytically)
    const float* w_qkv = (const float*)d_in[2];
    const float* b_qkv = (const float*)d_in[3];
    const float* w_out = (const float*)d_in[4];
    const float* b_out = (const float*)d_in[5];
    float* out = (float*)d_out;

    cudaFuncSetAttribute(flash_kernel,
                         cudaFuncAttributeMaxDynamicSharedMemorySize,
                         FLASH_SMEM_BYTES);

    // 1) QKV projection: M=4096, N=6144, K=2048
    {
        dim3 grid(6144 / 128, 4096 / 128);
        sgemm_kernel<0><<<grid, 256>>>(x, w_qkv, b_qkv, nullptr,
                                       BB * SS, 3 * HH, HH);
    }
    // 2) Causal flash attention: 16 query tiles x 32 heads
    {
        dim3 grid(SS / 128, BB * NHH);
        flash_kernel<<<grid, 256, FLASH_SMEM_BYTES>>>();
    }
    // 3) Output projection: M=4096, N=2048, K=2048
    {
        dim3 grid(2048 / 128, 4096 / 128);
        sgemm_kernel<1><<<grid, 256>>>(nullptr, w_out, b_out, out,
                                       BB * SS, HH, HH);
    }
}

// round 3
// speedup vs baseline: 1.9550x; 1.9550x over previous
#include <cuda_runtime.h>
#include <cuda_bf16.h>
#include <cstdint>
#include <math.h>

// Problem constants
#define BB   2
#define SS   2048
#define HH   2048
#define NHH  16
#define HDD  128
#define SCALE 0.08838834764831845f   // 1/sqrt(128)

// tcgen05 only exists in the sm_103a (arch-specific) compilation pass.
// The harness also emits a compute_103 PTX pass; keep it tcgen05-free.
#if defined(__CUDA_ARCH__) && defined(__CUDA_ARCH_FEAT_SM103_ALL)
#define HAS_TC 1
#else
#define HAS_TC 0
#endif

// ---------------------------------------------------------------------------
// Scratch (device globals: allocation-guard-safe)
// ---------------------------------------------------------------------------
__device__ float g_q[(size_t)BB * NHH * SS * HDD];    // [B,NH,S,HD] fp32
__device__ float g_k[(size_t)BB * NHH * SS * HDD];
__device__ float g_v[(size_t)BB * NHH * SS * HDD];
__device__ float g_ctx[(size_t)BB * SS * HH];         // [B,S,H] fp32

__device__ __nv_bfloat16 g_xh[8388608],   g_xl[8388608];    // x     [4096,2048]
__device__ __nv_bfloat16 g_wqh[12582912], g_wql[12582912];  // w_qkv [6144,2048]
__device__ __nv_bfloat16 g_ch[8388608],   g_cl[8388608];    // ctx   [4096,2048]
__device__ __nv_bfloat16 g_wo[4194304],   g_wol[4194304];   // w_out [2048,2048]

// ---------------------------------------------------------------------------
// PTX helpers (used only inside HAS_TC regions)
// ---------------------------------------------------------------------------
__device__ __forceinline__ uint32_t smem_to_u32(const void* p) {
    uint32_t a;
    asm("{ .reg .u64 t; cvta.to.shared.u64 t, %1; cvt.u32.u64 %0, t; }"
        : "=r"(a) : "l"(p));
    return a;
}
__device__ __forceinline__ uint32_t elect_one_pred() {
    uint32_t pred;
    asm volatile("{\n\t.reg .pred p;\n\telect.sync _|p, 0xFFFFFFFF;\n\t"
                 "selp.b32 %0, 1, 0, p;\n\t}" : "=r"(pred));
    return pred;
}
#define MBARRIER_INIT(addr, cnt) \
    asm volatile("mbarrier.init.shared.b64 [%0], %1;" :: "r"((uint32_t)(addr)), "r"((uint32_t)(cnt)) : "memory")
#define MBARRIER_WAIT_PARITY(addr, par) do {                                   \
    uint32_t _m = (uint32_t)(addr); uint32_t _p = (uint32_t)(par); uint32_t _d;\
    asm volatile("{\n\t.reg .pred p;\n\t"                                      \
        "mbarrier.try_wait.parity.acquire.cta.shared::cta.b64 p, [%1], %2;\n\t"\
        "selp.b32 %0, 1, 0, p;\n\t}" : "=r"(_d) : "r"(_m), "r"(_p) : "memory");\
    if (!_d) {                                                                 \
        asm volatile("{\n\t.reg .pred P1;\n\t"                                 \
        "WL_%=:\n\t"                                                           \
        "mbarrier.try_wait.parity.acquire.cta.shared::cta.b64 P1, [%0], %1, 0x989680;\n\t" \
        "@P1 bra.uni WD_%=;\n\tbra.uni WL_%=;\n\tWD_%=:\n\t}"                  \
        :: "r"(_m), "r"(_p) : "memory");                                       \
    }                                                                          \
} while (0)
#define TCGEN05_ALLOC(saddr, ncols) \
    asm volatile("tcgen05.alloc.cta_group::1.sync.aligned.shared::cta.b32 [%0], %1;" \
                 :: "r"((uint32_t)(saddr)), "r"((uint32_t)(ncols)) : "memory")
#define TCGEN05_DEALLOC(taddr, ncols) \
    asm volatile("tcgen05.dealloc.cta_group::1.sync.aligned.b32 %0, %1;" :: "r"(taddr), "r"((uint32_t)(ncols)))
#define TCGEN05_RELINQUISH() \
    asm volatile("tcgen05.relinquish_alloc_permit.cta_group::1.sync.aligned;")
#define TCGEN05_COMMIT(mbar) \
    asm volatile("tcgen05.commit.cta_group::1.mbarrier::arrive::one.shared::cluster.b64 [%0];" \
                 :: "r"((uint32_t)(mbar)) : "memory")
#define TCGEN05_WAIT_LD() asm volatile("tcgen05.wait::ld.sync.aligned;" ::: "memory")
#define TCGEN05_FENCE_AFTER() asm volatile("tcgen05.fence::after_thread_sync;" ::: "memory")
#define FENCE_PROXY_ASYNC() asm volatile("fence.proxy.async.shared::cta;" ::: "memory")
#define TCGEN05_LD_X32(r, taddr)                                               \
    asm volatile("tcgen05.ld.sync.aligned.32x32b.x32.b32 "                     \
        "{%0, %1, %2, %3, %4, %5, %6, %7, "                                    \
        " %8, %9, %10, %11, %12, %13, %14, %15, "                              \
        " %16, %17, %18, %19, %20, %21, %22, %23, "                            \
        " %24, %25, %26, %27, %28, %29, %30, %31}, [%32];"                     \
        : "=r"((r)[0]), "=r"((r)[1]), "=r"((r)[2]), "=r"((r)[3]),              \
          "=r"((r)[4]), "=r"((r)[5]), "=r"((r)[6]), "=r"((r)[7]),              \
          "=r"((r)[8]), "=r"((r)[9]), "=r"((r)[10]), "=r"((r)[11]),            \
          "=r"((r)[12]), "=r"((r)[13]), "=r"((r)[14]), "=r"((r)[15]),          \
          "=r"((r)[16]), "=r"((r)[17]), "=r"((r)[18]), "=r"((r)[19]),          \
          "=r"((r)[20]), "=r"((r)[21]), "=r"((r)[22]), "=r"((r)[23]),          \
          "=r"((r)[24]), "=r"((r)[25]), "=r"((r)[26]), "=r"((r)[27]),          \
          "=r"((r)[28]), "=r"((r)[29]), "=r"((r)[30]), "=r"((r)[31])           \
        : "r"(taddr))

#define SMEM_SWIZZLE_128B(b) ((b) ^ (((b) >> 3) & 0x70))
static constexpr uint64_t SMEM_DESC_BASE_SW128 =
    (uint64_t(2) << 61) | (uint64_t(1) << 46) | (uint64_t(64) << 32) | (uint64_t(1) << 16);
#define MAKE_SMEM_DESC(a) (SMEM_DESC_BASE_SW128 | ((uint64_t)((a) >> 4) & 0x3FFF))

#if HAS_TC
__device__ __forceinline__ void mma_ss_f16(uint32_t d, uint64_t a, uint64_t b,
                                           uint32_t idesc, bool acc) {
    uint32_t e = acc ? 1u : 0u;
    asm volatile(
        "{\n\t.reg .pred p;\n\t"
        "setp.ne.u32 p, %5, 0;\n\t"
        "tcgen05.mma.cta_group::1.kind::f16 [%0], %1, %2, %3, {%4, %4, %4, %4}, p;\n\t}"
        :: "r"(d), "l"(a), "l"(b), "r"(idesc), "r"(0u), "r"(e) : "memory");
}
#endif

// ---------------------------------------------------------------------------
// Split fp32 -> (hi, lo) bf16. Destination selected by template ID (no host
// symbol lookups needed). ID: 0=x, 1=w_qkv, 2=w_out, 3=ctx(src ignored).
// ---------------------------------------------------------------------------
template <int ID>
__global__ __launch_bounds__(256)
void split_kernel(const float* __restrict__ src, int n)
{
    __nv_bfloat16* hi;
    __nv_bfloat16* lo;
    const float* s = src;
    if (ID == 0) { hi = g_xh;  lo = g_xl; }
    else if (ID == 1) { hi = g_wqh; lo = g_wql; }
    else if (ID == 2) { hi = g_wo;  lo = g_wol; }
    else { hi = g_ch; lo = g_cl; s = g_ctx; }

    int i = (blockIdx.x * 256 + threadIdx.x) * 4;
    if (i >= n) return;
    float4 v = *(const float4*)(s + i);
    __nv_bfloat16 h0 = __float2bfloat16_rn(v.x);
    __nv_bfloat16 h1 = __float2bfloat16_rn(v.y);
    __nv_bfloat16 h2 = __float2bfloat16_rn(v.z);
    __nv_bfloat16 h3 = __float2bfloat16_rn(v.w);
    __nv_bfloat16 l0 = __float2bfloat16_rn(v.x - __bfloat162float(h0));
    __nv_bfloat16 l1 = __float2bfloat16_rn(v.y - __bfloat162float(h1));
    __nv_bfloat16 l2 = __float2bfloat16_rn(v.z - __bfloat162float(h2));
    __nv_bfloat16 l3 = __float2bfloat16_rn(v.w - __bfloat162float(h3));
    __nv_bfloat162* H = (__nv_bfloat162*)(hi + i);
    __nv_bfloat162* L = (__nv_bfloat162*)(lo + i);
    H[0] = __halves2bfloat162(h0, h1); H[1] = __halves2bfloat162(h2, h3);
    L[0] = __halves2bfloat162(l0, l1); L[1] = __halves2bfloat162(l2, l3);
}

// ---------------------------------------------------------------------------
// tcgen05 bf16x3 GEMM: C[M,N] = A[M,K] * W[N,K]^T + bias
// Tile 128x256, BK=64, 2-stage double buffer, 256 threads.
// MODE 0: A=g_x(h/l), B=g_wq(h/l), scatter fp32 q/k/v.
// MODE 1: A=g_c(h/l), B=g_wo(h/l), write fp32 C row-major.
// ---------------------------------------------------------------------------
#define GBM 128
#define GBN 256
#define GBK 64
#define STAGE_BYTES 98304            // A hi/lo 16K+16K, B hi/lo 32K+32K
#define GEMM_SMEM   (1024 + 2 * STAGE_BYTES)
#define GIDESC ((1u<<4) | (1u<<7) | (1u<<10) | ((GBN/8u)<<17) | ((GBM/16u)<<24))

#if HAS_TC
__device__ __forceinline__ void fill_stage(
    char* sm, int st,
    const __nv_bfloat16* __restrict__ Ah, const __nv_bfloat16* __restrict__ Al,
    const __nv_bfloat16* __restrict__ Bh, const __nv_bfloat16* __restrict__ Bl,
    int m0, int n0, int k0, int K, int tid)
{
    char* stage = sm + 1024 + st * STAGE_BYTES;
    char* dAh = stage;
    char* dAl = stage + 16384;
    char* dBh = stage + 32768;
    char* dBl = stage + 65536;
#pragma unroll
    for (int i = 0; i < 4; i++) {                 // A tiles: 128 rows x 64 bf16
        int q = tid + i * 256;                    // 0..1023
        int r = q >> 3, c = q & 7;
        uint32_t off = SMEM_SWIZZLE_128B((uint32_t)(r * 128 + c * 16));
        size_t src = (size_t)(m0 + r) * K + k0 + c * 8;
        *(float4*)(dAh + off) = *(const float4*)(Ah + src);
        *(float4*)(dAl + off) = *(const float4*)(Al + src);
    }
#pragma unroll
    for (int i = 0; i < 8; i++) {                 // B tiles: 256 rows x 64 bf16
        int q = tid + i * 256;                    // 0..2047
        int r = q >> 3, c = q & 7;
        uint32_t off = SMEM_SWIZZLE_128B((uint32_t)(r * 128 + c * 16));
        size_t src = (size_t)(n0 + r) * K + k0 + c * 8;
        *(float4*)(dBh + off) = *(const float4*)(Bh + src);
        *(float4*)(dBl + off) = *(const float4*)(Bl + src);
    }
}
#endif

template <int MODE>
__global__ __launch_bounds__(256)
void mma_gemm_kernel(const float* __restrict__ bias,
                     float* __restrict__ Cout,
                     int K, int Ntot)
{
#if HAS_TC
    extern __shared__ char sm[];
    const uint32_t su = smem_to_u32(sm);
    const int tid = threadIdx.x;
    const int wid = tid >> 5;
    const int lane = tid & 31;
    const int m0 = blockIdx.y * GBM;
    const int n0 = blockIdx.x * GBN;

    const __nv_bfloat16* Ah = (MODE == 0) ? g_xh  : g_ch;
    const __nv_bfloat16* Al = (MODE == 0) ? g_xl  : g_cl;
    const __nv_bfloat16* Bh = (MODE == 0) ? g_wqh : g_wo;
    const __nv_bfloat16* Bl = (MODE == 0) ? g_wql : g_wol;

    if (tid == 0) { MBARRIER_INIT(su + 0, 1); MBARRIER_INIT(su + 8, 1); }
    if (wid == 0) { TCGEN05_ALLOC(su + 16, 256); TCGEN05_RELINQUISH(); }
    __syncthreads();
    uint32_t tmem;
    asm volatile("ld.shared.b32 %0, [%1];" : "=r"(tmem) : "r"(su + 16));

    const int NC = K / GBK;   // 32
    fill_stage(sm, 0, Ah, Al, Bh, Bl, m0, n0, 0, K, tid);
    FENCE_PROXY_ASYNC();
    __syncthreads();

    for (int c = 0; c < NC; c++) {
        const int cur = c & 1;
        if (wid == 0) {
            if (elect_one_pred()) {
                uint32_t sb = su + 1024 + cur * STAGE_BYTES;
                uint64_t dAh = MAKE_SMEM_DESC(sb);
                uint64_t dAl = MAKE_SMEM_DESC(sb + 16384);
                uint64_t dBh = MAKE_SMEM_DESC(sb + 32768);
                uint64_t dBl = MAKE_SMEM_DESC(sb + 65536);
#pragma unroll
                for (int ks = 0; ks < 4; ks++)
                    mma_ss_f16(tmem, dAh + ks * 2, dBh + ks * 2, GIDESC, !(c == 0 && ks == 0));
#pragma unroll
                for (int ks = 0; ks < 4; ks++)
                    mma_ss_f16(tmem, dAh + ks * 2, dBl + ks * 2, GIDESC, true);
#pragma unroll
                for (int ks = 0; ks < 4; ks++)
                    mma_ss_f16(tmem, dAl + ks * 2, dBh + ks * 2, GIDESC, true);
                TCGEN05_COMMIT(su + cur * 8);
            }
        }
        if (c + 1 < NC) {
            const int nxt = cur ^ 1;
            if (c + 1 >= 2) {
                int arrival = (c - 1) >> 1;            // chunk c-1 used buf nxt
                MBARRIER_WAIT_PARITY(su + nxt * 8, arrival & 1);
            }
            fill_stage(sm, nxt, Ah, Al, Bh, Bl, m0, n0, (c + 1) * GBK, K, tid);
            FENCE_PROXY_ASYNC();
            __syncthreads();
        }
    }
    // wait for final chunk's MMAs
    MBARRIER_WAIT_PARITY(su + ((NC - 1) & 1) * 8, ((NC - 1) >> 1) & 1);
    TCGEN05_FENCE_AFTER();
    __syncthreads();

    // Epilogue: TMEM -> smem (stride 33) -> gmem, 32 cols per chunk
    float* ep = (float*)(sm + 1024);
    for (int c0 = 0; c0 < GBN; c0 += 32) {
        if (wid < 4) {
            uint32_t regs[32];
            TCGEN05_LD_X32(regs, tmem + c0);
            TCGEN05_WAIT_LD();
            int r = wid * 32 + lane;
#pragma unroll
            for (int c = 0; c < 32; c++) ep[r * 33 + c] = __uint_as_float(regs[c]);
        }
        __syncthreads();
        const int n_base = n0 + c0;
#pragma unroll
        for (int i = 0; i < 4; i++) {
            int idx = tid + i * 256;     // 0..1023
            int r = idx >> 3, q = idx & 7;
            float4 v;
            v.x = ep[r * 33 + q * 4 + 0] + bias[n_base + q * 4 + 0];
            v.y = ep[r * 33 + q * 4 + 1] + bias[n_base + q * 4 + 1];
            v.z = ep[r * 33 + q * 4 + 2] + bias[n_base + q * 4 + 2];
            v.w = ep[r * 33 + q * 4 + 3] + bias[n_base + q * 4 + 3];
            int m = m0 + r;
            if (MODE == 0) {
                int bb = m >> 11, s = m & 2047;
                int which = n_base >> 11;
                int rest  = n_base & 2047;
                int h = rest >> 7;
                int d = (rest & 127) + q * 4;
                float* dst = (which == 0) ? g_q : (which == 1) ? g_k : g_v;
                *(float4*)(dst + (((size_t)(bb * NHH + h)) * SS + s) * HDD + d) = v;
            } else {
                *(float4*)(Cout + (size_t)m * Ntot + n_base + q * 4) = v;
            }
        }
        __syncthreads();
    }
    if (wid == 0) TCGEN05_DEALLOC(tmem, 256);
#endif  // HAS_TC
}

// ---------------------------------------------------------------------------
// Causal flash attention, fp32 SIMT (round-1 proven)
// ---------------------------------------------------------------------------
#define FLASH_SMEM_FLOATS (128*132 + 32*132 + 128*132 + 32*132)
#define FLASH_SMEM_BYTES  (FLASH_SMEM_FLOATS * 4)

__global__ __launch_bounds__(256)
void flash_kernel()
{
    extern __shared__ float smf[];
    float* Qt = smf;
    float* Kt = Qt + 128 * 132;
    float* Ps = Kt + 32 * 132;
    float* Vs = Ps + 128 * 132;

    const int tid = threadIdx.x;
    const int tx = tid & 15;
    const int ty = tid >> 4;
    const int qt = blockIdx.x;
    const int bh = blockIdx.y;

    const float* Q  = g_q + (size_t)bh * SS * HDD;
    const float* Kp = g_k + (size_t)bh * SS * HDD;
    const float* Vp = g_v + (size_t)bh * SS * HDD;

#pragma unroll
    for (int it = 0; it < 16; it++) {
        int vec = tid + it * 256;
        int d4  = vec & 31;
        int r   = vec >> 5;
        float4 v = *(const float4*)(Q + ((size_t)qt * 128 + r) * HDD + d4 * 4);
        Qt[(d4 * 4 + 0) * 132 + r] = v.x;
        Qt[(d4 * 4 + 1) * 132 + r] = v.y;
        Qt[(d4 * 4 + 2) * 132 + r] = v.z;
        Qt[(d4 * 4 + 3) * 132 + r] = v.w;
    }

    float m_i[8], l_i[8], O[8][8];
#pragma unroll
    for (int i = 0; i < 8; i++) {
        m_i[i] = -1e30f; l_i[i] = 0.0f;
#pragma unroll
        for (int j = 0; j < 8; j++) O[i][j] = 0.0f;
    }
    __syncthreads();

    for (int kt = 0; kt <= qt; kt++) {
        float Sv[8][8];
#pragma unroll
        for (int i = 0; i < 8; i++)
#pragma unroll
            for (int j = 0; j < 8; j++) Sv[i][j] = 0.0f;

        for (int dc = 0; dc < 4; dc++) {
#pragma unroll
            for (int it = 0; it < 4; it++) {
                int vec = tid + it * 256;
                int d4  = vec & 7;
                int c   = vec >> 3;
                float4 v = *(const float4*)(Kp + ((size_t)kt * 128 + c) * HDD + dc * 32 + d4 * 4);
                Kt[(d4 * 4 + 0) * 132 + c] = v.x;
                Kt[(d4 * 4 + 1) * 132 + c] = v.y;
                Kt[(d4 * 4 + 2) * 132 + c] = v.z;
                Kt[(d4 * 4 + 3) * 132 + c] = v.w;
            }
            __syncthreads();
#pragma unroll
            for (int dl = 0; dl < 32; dl++) {
                int d = dc * 32 + dl;
                float4 q0 = *(const float4*)&Qt[d * 132 + ty * 8];
                float4 q1 = *(const float4*)&Qt[d * 132 + ty * 8 + 4];
                float4 k0 = *(const float4*)&Kt[dl * 132 + tx * 8];
                float4 k1 = *(const float4*)&Kt[dl * 132 + tx * 8 + 4];
                float qr[8] = {q0.x, q0.y, q0.z, q0.w, q1.x, q1.y, q1.z, q1.w};
                float kr[8] = {k0.x, k0.y, k0.z, k0.w, k1.x, k1.y, k1.z, k1.w};
#pragma unroll
                for (int i = 0; i < 8; i++)
#pragma unroll
                    for (int j = 0; j < 8; j++)
                        Sv[i][j] = fmaf(qr[i], kr[j], Sv[i][j]);
            }
            __syncthreads();
        }

        const bool diag = (kt == qt);
#pragma unroll
        for (int i = 0; i < 8; i++)
#pragma unroll
            for (int j = 0; j < 8; j++) {
                float s = Sv[i][j] * SCALE;
                if (diag && (tx * 8 + j) > (ty * 8 + i)) s = -1e30f;
                Sv[i][j] = s;
            }

#pragma unroll
        for (int i = 0; i < 8; i++) {
            float mx = Sv[i][0];
#pragma unroll
            for (int j = 1; j < 8; j++) mx = fmaxf(mx, Sv[i][j]);
            mx = fmaxf(mx, __shfl_xor_sync(0xffffffffu, mx, 8));
            mx = fmaxf(mx, __shfl_xor_sync(0xffffffffu, mx, 4));
            mx = fmaxf(mx, __shfl_xor_sync(0xffffffffu, mx, 2));
            mx = fmaxf(mx, __shfl_xor_sync(0xffffffffu, mx, 1));
            float mnew = fmaxf(m_i[i], mx);
            float corr = __expf(m_i[i] - mnew);
            m_i[i] = mnew;
            l_i[i] *= corr;
#pragma unroll
            for (int j = 0; j < 8; j++) O[i][j] *= corr;
            float rs = 0.0f;
#pragma unroll
            for (int j = 0; j < 8; j++) {
                float p = __expf(Sv[i][j] - mnew);
                Sv[i][j] = p;
                rs += p;
            }
            rs += __shfl_xor_sync(0xffffffffu, rs, 8);
            rs += __shfl_xor_sync(0xffffffffu, rs, 4);
            rs += __shfl_xor_sync(0xffffffffu, rs, 2);
            rs += __shfl_xor_sync(0xffffffffu, rs, 1);
            l_i[i] += rs;
        }

#pragma unroll
        for (int i = 0; i < 8; i++) {
            *(float4*)&Ps[(ty * 8 + i) * 132 + tx * 8] =
                make_float4(Sv[i][0], Sv[i][1], Sv[i][2], Sv[i][3]);
            *(float4*)&Ps[(ty * 8 + i) * 132 + tx * 8 + 4] =
                make_float4(Sv[i][4], Sv[i][5], Sv[i][6], Sv[i][7]);
        }

        for (int jc = 0; jc < 4; jc++) {
#pragma unroll
            for (int it = 0; it < 4; it++) {
                int vec = tid + it * 256;
                int d4  = vec & 31;
                int jl  = vec >> 5;
                *(float4*)&Vs[jl * 132 + d4 * 4] =
                    *(const float4*)(Vp + ((size_t)kt * 128 + jc * 32 + jl) * HDD + d4 * 4);
            }
            __syncthreads();
#pragma unroll
            for (int jl = 0; jl < 32; jl++) {
                int j = jc * 32 + jl;
                float pr[8];
#pragma unroll
                for (int i = 0; i < 8; i++) pr[i] = Ps[(ty * 8 + i) * 132 + j];
                float4 v0 = *(const float4*)&Vs[jl * 132 + tx * 8];
                float4 v1 = *(const float4*)&Vs[jl * 132 + tx * 8 + 4];
                float vr[8] = {v0.x, v0.y, v0.z, v0.w, v1.x, v1.y, v1.z, v1.w};
#pragma unroll
                for (int i = 0; i < 8; i++)
#pragma unroll
                    for (int jj = 0; jj < 8; jj++)
                        O[i][jj] = fmaf(pr[i], vr[jj], O[i][jj]);
            }
            __syncthreads();
        }
    }

    const int b = bh >> 4, h = bh & 15;
#pragma unroll
    for (int i = 0; i < 8; i++) {
        float inv = 1.0f / l_i[i];
        int s = qt * 128 + ty * 8 + i;
        float* dst = g_ctx + ((size_t)b * SS + s) * HH + h * HDD + tx * 8;
        *(float4*)(dst)     = make_float4(O[i][0] * inv, O[i][1] * inv,
                                          O[i][2] * inv, O[i][3] * inv);
        *(float4*)(dst + 4) = make_float4(O[i][4] * inv, O[i][5] * inv,
                                          O[i][6] * inv, O[i][7] * inv);
    }
}

// ---------------------------------------------------------------------------
// Launch sequence
// ---------------------------------------------------------------------------
extern "C" void kernel_launch(void* const* d_in, const int* in_sizes, int n_in,
                              void* d_out, int out_size)
{
    (void)in_sizes; (void)n_in; (void)out_size;
    const float* x     = (const float*)d_in[0];
    const float* w_qkv = (const float*)d_in[2];
    const float* b_qkv = (const float*)d_in[3];
    const float* w_out = (const float*)d_in[4];
    const float* b_out = (const float*)d_in[5];
    float* out = (float*)d_out;

    cudaFuncSetAttribute(mma_gemm_kernel<0>,
        cudaFuncAttributeMaxDynamicSharedMemorySize, GEMM_SMEM);
    cudaFuncSetAttribute(mma_gemm_kernel<1>,
        cudaFuncAttributeMaxDynamicSharedMemorySize, GEMM_SMEM);
    cudaFuncSetAttribute(flash_kernel,
        cudaFuncAttributeMaxDynamicSharedMemorySize, FLASH_SMEM_BYTES);

    // 1) Split fp32 operands into bf16 hi/lo
    split_kernel<0><<<8388608  / 1024, 256>>>(x,     8388608);
    split_kernel<1><<<12582912 / 1024, 256>>>(w_qkv, 12582912);
    split_kernel<2><<<4194304  / 1024, 256>>>(w_out, 4194304);

    // 2) QKV projection: M=4096, N=6144, K=2048 (tcgen05 bf16x3)
    {
        dim3 grid(6144 / GBN, 4096 / GBM);
        mma_gemm_kernel<0><<<grid, 256, GEMM_SMEM>>>(b_qkv, nullptr, 2048, 6144);
    }

    // 3) Causal flash attention (fp32 SIMT)
    {
        dim3 grid(SS / 128, BB * NHH);
        flash_kernel<<<grid, 256, FLASH_SMEM_BYTES>>>();
    }

    // 4) Split ctx, then output projection: M=4096, N=2048, K=2048
    split_kernel<3><<<8388608 / 1024, 256>>>(nullptr, 8388608);
    {
        dim3 grid(2048 / GBN, 4096 / GBM);
        mma_gemm_kernel<1><<<grid, 256, GEMM_SMEM>>>(b_out, out, 2048, 2048);
    }
}

// round 5
// speedup vs baseline: 6.0380x; 3.0886x over previous
#include <cuda_runtime.h>
#include <cuda_bf16.h>
#include <cstdint>
#include <math.h>

// Problem constants
#define BB   2
#define SS   2048
#define HH   2048
#define NHH  16
#define HDD  128
#define SCALE 0.08838834764831845f   // 1/sqrt(128)

// tcgen05 only exists in the sm_103a (arch-specific) compilation pass.
#if defined(__CUDA_ARCH__) && defined(__CUDA_ARCH_FEAT_SM103_ALL)
#define HAS_TC 1
#else
#define HAS_TC 0
#endif

// ---------------------------------------------------------------------------
// Scratch (device globals: allocation-guard-safe)
// ---------------------------------------------------------------------------
__device__ float g_ctx[(size_t)BB * SS * HH];               // [B,S,H] fp32

// q/k: [B,NH,S,HD] bf16 hi/lo (q pre-scaled by SCALE). v: [B,NH,HD,S] (transposed)
__device__ __nv_bfloat16 gq_h[8388608], gq_l[8388608];
__device__ __nv_bfloat16 gk_h[8388608], gk_l[8388608];
__device__ __nv_bfloat16 gv_h[8388608], gv_l[8388608];

__device__ __nv_bfloat16 g_xh[8388608],   g_xl[8388608];    // x     [4096,2048]
__device__ __nv_bfloat16 g_wqh[12582912], g_wql[12582912];  // w_qkv [6144,2048]
__device__ __nv_bfloat16 g_ch[8388608],   g_cl[8388608];    // ctx   [4096,2048]
__device__ __nv_bfloat16 g_wo[4194304],   g_wol[4194304];   // w_out [2048,2048]

// ---------------------------------------------------------------------------
// PTX helpers
// ---------------------------------------------------------------------------
__device__ __forceinline__ uint32_t smem_to_u32(const void* p) {
    uint32_t a;
    asm("{ .reg .u64 t; cvta.to.shared.u64 t, %1; cvt.u32.u64 %0, t; }"
        : "=r"(a) : "l"(p));
    return a;
}
__device__ __forceinline__ uint32_t elect_one_pred() {
    uint32_t pred;
    asm volatile("{\n\t.reg .pred p;\n\telect.sync _|p, 0xFFFFFFFF;\n\t"
                 "selp.b32 %0, 1, 0, p;\n\t}" : "=r"(pred));
    return pred;
}
#define MBARRIER_INIT(addr, cnt) \
    asm volatile("mbarrier.init.shared.b64 [%0], %1;" :: "r"((uint32_t)(addr)), "r"((uint32_t)(cnt)) : "memory")
#define MBARRIER_WAIT_PARITY(addr, par) do {                                   \
    uint32_t _m = (uint32_t)(addr); uint32_t _p = (uint32_t)(par); uint32_t _d;\
    asm volatile("{\n\t.reg .pred p;\n\t"                                      \
        "mbarrier.try_wait.parity.acquire.cta.shared::cta.b64 p, [%1], %2;\n\t"\
        "selp.b32 %0, 1, 0, p;\n\t}" : "=r"(_d) : "r"(_m), "r"(_p) : "memory");\
    if (!_d) {                                                                 \
        asm volatile("{\n\t.reg .pred P1;\n\t"                                 \
        "WL_%=:\n\t"                                                           \
        "mbarrier.try_wait.parity.acquire.cta.shared::cta.b64 P1, [%0], %1, 0x989680;\n\t" \
        "@P1 bra.uni WD_%=;\n\tbra.uni WL_%=;\n\tWD_%=:\n\t}"                  \
        :: "r"(_m), "r"(_p) : "memory");                                       \
    }                                                                          \
} while (0)
#define TCGEN05_ALLOC(saddr, ncols) \
    asm volatile("tcgen05.alloc.cta_group::1.sync.aligned.shared::cta.b32 [%0], %1;" \
                 :: "r"((uint32_t)(saddr)), "r"((uint32_t)(ncols)) : "memory")
#define TCGEN05_DEALLOC(taddr, ncols) \
    asm volatile("tcgen05.dealloc.cta_group::1.sync.aligned.b32 %0, %1;" :: "r"(taddr), "r"((uint32_t)(ncols)))
#define TCGEN05_RELINQUISH() \
    asm volatile("tcgen05.relinquish_alloc_permit.cta_group::1.sync.aligned;")
#define TCGEN05_COMMIT(mbar) \
    asm volatile("tcgen05.commit.cta_group::1.mbarrier::arrive::one.shared::cluster.b64 [%0];" \
                 :: "r"((uint32_t)(mbar)) : "memory")
#define TCGEN05_WAIT_LD() asm volatile("tcgen05.wait::ld.sync.aligned;" ::: "memory")
#define TCGEN05_FENCE_BEFORE() asm volatile("tcgen05.fence::before_thread_sync;" ::: "memory")
#define TCGEN05_FENCE_AFTER()  asm volatile("tcgen05.fence::after_thread_sync;" ::: "memory")
#define FENCE_PROXY_ASYNC() asm volatile("fence.proxy.async.shared::cta;" ::: "memory")
#define CP_ASYNC16(dst, src) \
    asm volatile("cp.async.cg.shared.global [%0], [%1], 16;" :: "r"((uint32_t)(dst)), "l"(src) : "memory")
#define CP_COMMIT() asm volatile("cp.async.commit_group;" ::: "memory")
#define CP_WAIT0()  asm volatile("cp.async.wait_group 0;" ::: "memory")
#define TCGEN05_LD_X32(r, taddr)                                               \
    asm volatile("tcgen05.ld.sync.aligned.32x32b.x32.b32 "                     \
        "{%0, %1, %2, %3, %4, %5, %6, %7, "                                    \
        " %8, %9, %10, %11, %12, %13, %14, %15, "                              \
        " %16, %17, %18, %19, %20, %21, %22, %23, "                            \
        " %24, %25, %26, %27, %28, %29, %30, %31}, [%32];"                     \
        : "=r"((r)[0]), "=r"((r)[1]), "=r"((r)[2]), "=r"((r)[3]),              \
          "=r"((r)[4]), "=r"((r)[5]), "=r"((r)[6]), "=r"((r)[7]),              \
          "=r"((r)[8]), "=r"((r)[9]), "=r"((r)[10]), "=r"((r)[11]),            \
          "=r"((r)[12]), "=r"((r)[13]), "=r"((r)[14]), "=r"((r)[15]),          \
          "=r"((r)[16]), "=r"((r)[17]), "=r"((r)[18]), "=r"((r)[19]),          \
          "=r"((r)[20]), "=r"((r)[21]), "=r"((r)[22]), "=r"((r)[23]),          \
          "=r"((r)[24]), "=r"((r)[25]), "=r"((r)[26]), "=r"((r)[27]),          \
          "=r"((r)[28]), "=r"((r)[29]), "=r"((r)[30]), "=r"((r)[31])           \
        : "r"(taddr))

#define SMEM_SWIZZLE_128B(b) ((b) ^ (((b) >> 3) & 0x70))
static constexpr uint64_t SMEM_DESC_BASE_SW128 =
    (uint64_t(2) << 61) | (uint64_t(1) << 46) | (uint64_t(64) << 32) | (uint64_t(1) << 16);
#define MAKE_SMEM_DESC(a) (SMEM_DESC_BASE_SW128 | ((uint64_t)((a) >> 4) & 0x3FFF))

#if HAS_TC
__device__ __forceinline__ void mma_ss_f16(uint32_t d, uint64_t a, uint64_t b,
                                           uint32_t idesc, bool acc) {
    uint32_t e = acc ? 1u : 0u;
    asm volatile(
        "{\n\t.reg .pred p;\n\t"
        "setp.ne.u32 p, %5, 0;\n\t"
        "tcgen05.mma.cta_group::1.kind::f16 [%0], %1, %2, %3, {%4, %4, %4, %4}, p;\n\t}"
        :: "r"(d), "l"(a), "l"(b), "r"(idesc), "r"(0u), "r"(e) : "memory");
}
#endif

__device__ __forceinline__ void bf16_split(float v, __nv_bfloat16& h, __nv_bfloat16& l) {
    h = __float2bfloat16_rn(v);
    l = __float2bfloat16_rn(v - __bfloat162float(h));
}

// ---------------------------------------------------------------------------
// Split fp32 -> (hi, lo) bf16. ID: 0=x, 1=w_qkv, 2=w_out, 3=ctx
// ---------------------------------------------------------------------------
template <int ID>
__global__ __launch_bounds__(256)
void split_kernel(const float* __restrict__ src, int n)
{
    __nv_bfloat16* hi;
    __nv_bfloat16* lo;
    const float* s = src;
    if (ID == 0) { hi = g_xh;  lo = g_xl; }
    else if (ID == 1) { hi = g_wqh; lo = g_wql; }
    else if (ID == 2) { hi = g_wo;  lo = g_wol; }
    else { hi = g_ch; lo = g_cl; s = g_ctx; }

    int i = (blockIdx.x * 256 + threadIdx.x) * 4;
    if (i >= n) return;
    float4 v = *(const float4*)(s + i);
    __nv_bfloat16 h0, h1, h2, h3, l0, l1, l2, l3;
    bf16_split(v.x, h0, l0); bf16_split(v.y, h1, l1);
    bf16_split(v.z, h2, l2); bf16_split(v.w, h3, l3);
    __nv_bfloat162* H = (__nv_bfloat162*)(hi + i);
    __nv_bfloat162* L = (__nv_bfloat162*)(lo + i);
    H[0] = __halves2bfloat162(h0, h1); H[1] = __halves2bfloat162(h2, h3);
    L[0] = __halves2bfloat162(l0, l1); L[1] = __halves2bfloat162(l2, l3);
}

// ---------------------------------------------------------------------------
// tcgen05 bf16x3 GEMM with cp.async pipelined fills. 128x256, BK=64, 2 stages.
// MODE 0: scatter q/k/v as bf16 hi/lo (q scaled; v head-transposed).
// MODE 1: write fp32 C (+bias) row-major.
// ---------------------------------------------------------------------------
#define GBM 128
#define GBN 256
#define GBK 64
#define STAGE_BYTES 98304
#define GEMM_SMEM   (1024 + 2 * STAGE_BYTES)
#define GIDESC ((1u<<4) | (1u<<7) | (1u<<10) | ((GBN/8u)<<17) | ((GBM/16u)<<24))

#if HAS_TC
__device__ __forceinline__ void fill_stage_async(
    uint32_t su, int st,
    const __nv_bfloat16* __restrict__ Ah, const __nv_bfloat16* __restrict__ Al,
    const __nv_bfloat16* __restrict__ Bh, const __nv_bfloat16* __restrict__ Bl,
    int m0, int n0, int k0, int K, int tid)
{
    uint32_t stage = su + 1024 + st * STAGE_BYTES;
#pragma unroll
    for (int i = 0; i < 4; i++) {                 // A: 128 rows x 64 bf16
        int q = tid + i * 256;
        int r = q >> 3, c = q & 7;
        uint32_t off = SMEM_SWIZZLE_128B((uint32_t)(r * 128 + c * 16));
        size_t src = (size_t)(m0 + r) * K + k0 + c * 8;
        CP_ASYNC16(stage + off,         Ah + src);
        CP_ASYNC16(stage + 16384 + off, Al + src);
    }
#pragma unroll
    for (int i = 0; i < 8; i++) {                 // B: 256 rows x 64 bf16
        int q = tid + i * 256;
        int r = q >> 3, c = q & 7;
        uint32_t off = SMEM_SWIZZLE_128B((uint32_t)(r * 128 + c * 16));
        size_t src = (size_t)(n0 + r) * K + k0 + c * 8;
        CP_ASYNC16(stage + 32768 + off, Bh + src);
        CP_ASYNC16(stage + 65536 + off, Bl + src);
    }
    CP_COMMIT();
}
#endif

template <int MODE>
__global__ __launch_bounds__(256)
void mma_gemm_kernel(const float* __restrict__ bias,
                     float* __restrict__ Cout,
                     int K, int Ntot)
{
#if HAS_TC
    extern __shared__ char sm[];
    const uint32_t su = smem_to_u32(sm);
    const int tid = threadIdx.x;
    const int wid = tid >> 5;
    const int lane = tid & 31;
    const int m0 = blockIdx.y * GBM;
    const int n0 = blockIdx.x * GBN;

    const __nv_bfloat16* Ah = (MODE == 0) ? g_xh  : g_ch;
    const __nv_bfloat16* Al = (MODE == 0) ? g_xl  : g_cl;
    const __nv_bfloat16* Bh = (MODE == 0) ? g_wqh : g_wo;
    const __nv_bfloat16* Bl = (MODE == 0) ? g_wql : g_wol;

    if (tid == 0) { MBARRIER_INIT(su + 0, 1); MBARRIER_INIT(su + 8, 1); }
    if (wid == 0) { TCGEN05_ALLOC(su + 16, 256); TCGEN05_RELINQUISH(); }
    __syncthreads();
    uint32_t tmem;
    asm volatile("ld.shared.b32 %0, [%1];" : "=r"(tmem) : "r"(su + 16));

    const int NC = K / GBK;   // 32
    fill_stage_async(su, 0, Ah, Al, Bh, Bl, m0, n0, 0, K, tid);

    for (int c = 0; c < NC; c++) {
        const int cur = c & 1;
        CP_WAIT0();
        FENCE_PROXY_ASYNC();
        __syncthreads();
        if (wid == 0) {
            if (elect_one_pred()) {
                uint32_t sb = su + 1024 + cur * STAGE_BYTES;
                uint64_t dAh = MAKE_SMEM_DESC(sb);
                uint64_t dAl = MAKE_SMEM_DESC(sb + 16384);
                uint64_t dBh = MAKE_SMEM_DESC(sb + 32768);
                uint64_t dBl = MAKE_SMEM_DESC(sb + 65536);
#pragma unroll
                for (int ks = 0; ks < 4; ks++)
                    mma_ss_f16(tmem, dAh + ks * 2, dBh + ks * 2, GIDESC, !(c == 0 && ks == 0));
#pragma unroll
                for (int ks = 0; ks < 4; ks++)
                    mma_ss_f16(tmem, dAh + ks * 2, dBl + ks * 2, GIDESC, true);
#pragma unroll
                for (int ks = 0; ks < 4; ks++)
                    mma_ss_f16(tmem, dAl + ks * 2, dBh + ks * 2, GIDESC, true);
                TCGEN05_COMMIT(su + cur * 8);
            }
        }
        if (c + 1 < NC) {
            if (c >= 1)   // MMA(c-1) (buffer cur^1) must finish before refill
                MBARRIER_WAIT_PARITY(su + ((c - 1) & 1) * 8, ((c - 1) >> 1) & 1);
            fill_stage_async(su, cur ^ 1, Ah, Al, Bh, Bl, m0, n0, (c + 1) * GBK, K, tid);
        }
    }
    MBARRIER_WAIT_PARITY(su + ((NC - 1) & 1) * 8, ((NC - 1) >> 1) & 1);
    TCGEN05_FENCE_AFTER();
    __syncthreads();

    // Epilogue: TMEM -> smem (stride 33) -> gmem, 32 cols per chunk
    float* ep = (float*)(sm + 1024);
    for (int c0 = 0; c0 < GBN; c0 += 32) {
        if (wid < 4) {
            uint32_t regs[32];
            TCGEN05_LD_X32(regs, tmem + c0);
            TCGEN05_WAIT_LD();
            int r = wid * 32 + lane;
#pragma unroll
            for (int c = 0; c < 32; c++) ep[r * 33 + c] = __uint_as_float(regs[c]);
        }
        __syncthreads();
        const int n_base = n0 + c0;
        const int which = n_base >> 11;

        if (MODE == 0 && which == 2) {
            // v: head-transposed bf16 hi/lo, coalesced along s
            int rest = n_base & 2047;
            int h = rest >> 7, dbase = rest & 127;
            size_t head = (size_t)((m0 >> 11) * NHH + h);
            int s0 = m0 & 2047;
#pragma unroll
            for (int k4 = 0; k4 < 4; k4++) {
                int col = wid * 4 + k4;
                float bval = bias[n_base + col];
                __nv_bfloat16* dh = gv_h + (head * HDD + dbase + col) * SS + s0;
                __nv_bfloat16* dl = gv_l + (head * HDD + dbase + col) * SS + s0;
#pragma unroll
                for (int j = 0; j < 4; j++) {
                    int r = lane + j * 32;
                    float val = ep[r * 33 + col] + bval;
                    __nv_bfloat16 hh, ll;
                    bf16_split(val, hh, ll);
                    dh[r] = hh; dl[r] = ll;
                }
            }
        } else {
#pragma unroll
            for (int i = 0; i < 4; i++) {
                int idx = tid + i * 256;
                int r = idx >> 3, q = idx & 7;
                float4 v;
                v.x = ep[r * 33 + q * 4 + 0] + bias[n_base + q * 4 + 0];
                v.y = ep[r * 33 + q * 4 + 1] + bias[n_base + q * 4 + 1];
                v.z = ep[r * 33 + q * 4 + 2] + bias[n_base + q * 4 + 2];
                v.w = ep[r * 33 + q * 4 + 3] + bias[n_base + q * 4 + 3];
                int m = m0 + r;
                if (MODE == 0) {
                    int bb = m >> 11, s = m & 2047;
                    int rest = n_base & 2047;
                    int h = rest >> 7;
                    int d = (rest & 127) + q * 4;
                    size_t off = (((size_t)(bb * NHH + h)) * SS + s) * HDD + d;
                    if (which == 0) { v.x *= SCALE; v.y *= SCALE; v.z *= SCALE; v.w *= SCALE; }
                    __nv_bfloat16 h0, h1, h2, h3, l0, l1, l2, l3;
                    bf16_split(v.x, h0, l0); bf16_split(v.y, h1, l1);
                    bf16_split(v.z, h2, l2); bf16_split(v.w, h3, l3);
                    __nv_bfloat16* dh = (which == 0) ? gq_h : gk_h;
                    __nv_bfloat16* dl = (which == 0) ? gq_l : gk_l;
                    ((__nv_bfloat162*)(dh + off))[0] = __halves2bfloat162(h0, h1);
                    ((__nv_bfloat162*)(dh + off))[1] = __halves2bfloat162(h2, h3);
                    ((__nv_bfloat162*)(dl + off))[0] = __halves2bfloat162(l0, l1);
                    ((__nv_bfloat162*)(dl + off))[1] = __halves2bfloat162(l2, l3);
                } else {
                    *(float4*)(Cout + (size_t)m * Ntot + n_base + q * 4) = v;
                }
            }
        }
        __syncthreads();
    }
    if (wid == 0) TCGEN05_DEALLOC(tmem, 256);
#endif
}

// ---------------------------------------------------------------------------
// Causal flash attention, tcgen05 bf16x3.
// CTA = 128 q x one (b,h); kv tiles of 64; 256 threads (8 warps).
// Warp w: rows (w&3)*32+lane, column-half w>>2.
// S in TMEM cols 0..63 (fp32); D = P*V in cols 64..191 (fp32, fresh per tile).
// SMEM: Q hi/lo (2 dc chunks each), K hi/lo, V hi/lo x2 stages, P hi/lo.
// ---------------------------------------------------------------------------
#define FL_Q    1024                       // hi: 2x16384, lo at +32768
#define FL_K    (FL_Q + 65536)             // hi: 2x8192,  lo at +16384
#define FL_V    (FL_K + 32768)             // stage: hi 16384 + lo 16384; x2
#define FL_P    (FL_V + 65536)             // hi 16384, lo 16384
#define FL_RED  (FL_P + 32768)
#define FL_SMEM (FL_RED + 2048)            // = 199,680 bytes
#define FIDESC_QK ((1u<<4) | (1u<<7) | (1u<<10) | (8u<<17)  | (8u<<24))   // N=64
#define FIDESC_PV ((1u<<4) | (1u<<7) | (1u<<10) | (16u<<17) | (8u<<24))   // N=128

#if HAS_TC
__device__ __forceinline__ void flash_fill_k(
    uint32_t su, const __nv_bfloat16* Kh, const __nv_bfloat16* Kl, int kt, int tid)
{
#pragma unroll
    for (int it = 0; it < 4; it++) {
        int vec = tid + it * 256;            // 0..1023
        int r = vec >> 4;                    // kv 0..63
        int dc = (vec >> 3) & 1;
        int i = vec & 7;
        uint32_t off = dc * 8192 + SMEM_SWIZZLE_128B((uint32_t)(r * 128 + i * 16));
        size_t src = ((size_t)kt * 64 + r) * HDD + dc * 64 + i * 8;
        CP_ASYNC16(su + FL_K + off,         Kh + src);
        CP_ASYNC16(su + FL_K + 16384 + off, Kl + src);
    }
    CP_COMMIT();
}
__device__ __forceinline__ void flash_fill_v(
    uint32_t su, const __nv_bfloat16* Vh, const __nv_bfloat16* Vl,
    int kt, int buf, int tid)
{
    uint32_t base = su + FL_V + buf * 32768;
#pragma unroll
    for (int it = 0; it < 4; it++) {
        int vec = tid + it * 256;            // 0..1023
        int d = vec >> 3;                    // 0..127
        int i = vec & 7;
        uint32_t off = SMEM_SWIZZLE_128B((uint32_t)(d * 128 + i * 16));
        size_t src = (size_t)d * SS + kt * 64 + i * 8;
        CP_ASYNC16(base + off,         Vh + src);
        CP_ASYNC16(base + 16384 + off, Vl + src);
    }
    CP_COMMIT();
}
#endif

__global__ __launch_bounds__(256)
void flash_tc_kernel()
{
#if HAS_TC
    extern __shared__ char sm[];
    const uint32_t su = smem_to_u32(sm);
    const int tid = threadIdx.x;
    const int wid = tid >> 5;
    const int lane = tid & 31;
    const int half = wid >> 2;
    const int row = (wid & 3) * 32 + lane;
    const int qt = gridDim.x - 1 - blockIdx.x;   // longest q-tiles first
    const int bh = blockIdx.y;

    const size_t hoff = (size_t)bh * SS * HDD;
    const __nv_bfloat16 *Qh = gq_h + hoff, *Ql = gq_l + hoff;
    const __nv_bfloat16 *Kh = gk_h + hoff, *Kl = gk_l + hoff;
    const __nv_bfloat16 *Vh = gv_h + hoff, *Vl = gv_l + hoff;

    if (tid == 0) { MBARRIER_INIT(su + 16, 1); MBARRIER_INIT(su + 24, 1); }
    if (wid == 0) { TCGEN05_ALLOC(su + 0, 256); TCGEN05_RELINQUISH(); }
    __syncthreads();
    uint32_t tmem;
    asm volatile("ld.shared.b32 %0, [%1];" : "=r"(tmem) : "r"(su + 0));

    // Q tile [128 q][128 d] hi/lo, 2 dc chunks each
#pragma unroll
    for (int it = 0; it < 8; it++) {
        int vec = tid + it * 256;            // 0..2047
        int r = vec >> 4;                    // 0..127
        int dc = (vec >> 3) & 1;
        int i = vec & 7;
        uint32_t off = dc * 16384 + SMEM_SWIZZLE_128B((uint32_t)(r * 128 + i * 16));
        size_t src = ((size_t)qt * 128 + r) * HDD + dc * 64 + i * 8;
        CP_ASYNC16(su + FL_Q + off,         Qh + src);
        CP_ASYNC16(su + FL_Q + 32768 + off, Ql + src);
    }
    CP_COMMIT();
    flash_fill_k(su, Kh, Kl, 0, tid);
    flash_fill_v(su, Vh, Vl, 0, 0, tid);

    float m_i = -1e30f, l_i = 0.0f;
    float O[64];
#pragma unroll
    for (int j = 0; j < 64; j++) O[j] = 0.0f;

    float* redm = (float*)(sm + FL_RED);          // [2][128]
    float* reds = (float*)(sm + FL_RED + 1024);   // [2][128]
    const int KT = 2 * qt + 2;
    const int grow = qt * 128 + row;

    for (int kt = 0; kt < KT; kt++) {
        CP_WAIT0();
        FENCE_PROXY_ASYNC();
        __syncthreads();
        TCGEN05_FENCE_AFTER();

        // S = Q K^T : 3 passes (qh*kh, qh*kl, ql*kh), 24 dispatches
        if (wid == 0) {
            if (elect_one_pred()) {
                bool first = true;
#pragma unroll
                for (int p = 0; p < 3; p++) {
                    uint32_t ab = su + FL_Q + ((p == 2) ? 32768 : 0);
                    uint32_t bb2 = su + FL_K + ((p == 1) ? 16384 : 0);
#pragma unroll
                    for (int dc = 0; dc < 2; dc++) {
                        uint64_t a = MAKE_SMEM_DESC(ab + dc * 16384);
                        uint64_t b = MAKE_SMEM_DESC(bb2 + dc * 8192);
#pragma unroll
                        for (int st = 0; st < 4; st++) {
                            mma_ss_f16(tmem, a + st * 2, b + st * 2, FIDESC_QK, !first);
                            first = false;
                        }
                    }
                }
                TCGEN05_COMMIT(su + 16);
            }
        }
        MBARRIER_WAIT_PARITY(su + 16, kt & 1);
        TCGEN05_FENCE_AFTER();

        // prefetch next tiles: K safe now (QK done); V into the OTHER buffer
        if (kt + 1 < KT) {
            flash_fill_k(su, Kh, Kl, kt + 1, tid);
            flash_fill_v(su, Vh, Vl, kt + 1, (kt + 1) & 1, tid);
        }

        // LDTM S (this warp's 32 cols), mask, online softmax
        uint32_t sreg[32];
        TCGEN05_LD_X32(sreg, tmem + half * 32);
        TCGEN05_WAIT_LD();

        const int gc0 = kt * 64 + half * 32;
        float sv[32];
        float mx = -1e30f;
#pragma unroll
        for (int c = 0; c < 32; c++) {
            float s = __uint_as_float(sreg[c]);
            if (gc0 + c > grow) s = -1e30f;
            sv[c] = s;
            mx = fmaxf(mx, s);
        }
        redm[half * 128 + row] = mx;
        __syncthreads();
        mx = fmaxf(mx, redm[(1 - half) * 128 + row]);
        float mnew = fmaxf(m_i, mx);
        float corr = __expf(m_i - mnew);
        m_i = mnew;
        float ps = 0.0f;
#pragma unroll
        for (int c = 0; c < 32; c++) {
            float p = __expf(sv[c] - mnew);
            sv[c] = p;
            ps += p;
        }
        reds[half * 128 + row] = ps;
        __syncthreads();
        ps += reds[(1 - half) * 128 + row];
        l_i = l_i * corr + ps;

        // P -> smem bf16 hi/lo ([128 q][64 kv], this thread's 32 kv)
#pragma unroll
        for (int i = 0; i < 4; i++) {
            uint32_t wh[4], wl[4];
#pragma unroll
            for (int g = 0; g < 4; g++) {
                __nv_bfloat16 h0, l0, h1, l1;
                bf16_split(sv[i * 8 + g * 2 + 0], h0, l0);
                bf16_split(sv[i * 8 + g * 2 + 1], h1, l1);
                __nv_bfloat162 ph = __halves2bfloat162(h0, h1);
                __nv_bfloat162 pl = __halves2bfloat162(l0, l1);
                wh[g] = *(uint32_t*)&ph;
                wl[g] = *(uint32_t*)&pl;
            }
            uint32_t off = SMEM_SWIZZLE_128B((uint32_t)(row * 128 + half * 64 + i * 16));
            asm volatile("st.shared.v4.b32 [%0], {%1,%2,%3,%4};"
                :: "r"(su + FL_P + off), "r"(wh[0]), "r"(wh[1]), "r"(wh[2]), "r"(wh[3]) : "memory");
            asm volatile("st.shared.v4.b32 [%0], {%1,%2,%3,%4};"
                :: "r"(su + FL_P + 16384 + off), "r"(wl[0]), "r"(wl[1]), "r"(wl[2]), "r"(wl[3]) : "memory");
        }
        TCGEN05_FENCE_BEFORE();        // order S reads before barrier
        FENCE_PROXY_ASYNC();           // P stores visible to MMA
        __syncthreads();
        TCGEN05_FENCE_AFTER();

        // D = P V : 3 passes (ph*vh, ph*vl, pl*vh), 12 dispatches; V buf = kt&1
        if (wid == 0) {
            if (elect_one_pred()) {
                uint32_t vbase = su + FL_V + (kt & 1) * 32768;
                bool first = true;
#pragma unroll
                for (int p = 0; p < 3; p++) {
                    uint64_t a = MAKE_SMEM_DESC(su + FL_P + ((p == 2) ? 16384 : 0));
                    uint64_t b = MAKE_SMEM_DESC(vbase + ((p == 1) ? 16384 : 0));
#pragma unroll
                    for (int st = 0; st < 4; st++) {
                        mma_ss_f16(tmem + 64, a + st * 2, b + st * 2, FIDESC_PV, !first);
                        first = false;
                    }
                }
                TCGEN05_COMMIT(su + 24);
            }
        }
        MBARRIER_WAIT_PARITY(su + 24, kt & 1);
        TCGEN05_FENCE_AFTER();

        // O = O*corr + D (this warp's 64 d-columns)
        uint32_t dreg[32];
        TCGEN05_LD_X32(dreg, tmem + 64 + half * 64);
        TCGEN05_WAIT_LD();
#pragma unroll
        for (int j = 0; j < 32; j++)
            O[j] = O[j] * corr + __uint_as_float(dreg[j]);
        TCGEN05_LD_X32(dreg, tmem + 64 + half * 64 + 32);
        TCGEN05_WAIT_LD();
#pragma unroll
        for (int j = 0; j < 32; j++)
            O[32 + j] = O[32 + j] * corr + __uint_as_float(dreg[j]);
        TCGEN05_FENCE_BEFORE();
        __syncthreads();
    }

    // Finalize: ctx[b][s][h*128 + half*64 + j]
    const float inv = 1.0f / l_i;
    const int b = bh >> 4, h = bh & 15;
    const int s = qt * 128 + row;
    float* dst = g_ctx + ((size_t)b * SS + s) * HH + h * HDD + half * 64;
#pragma unroll
    for (int i = 0; i < 16; i++) {
        *(float4*)(dst + i * 4) = make_float4(O[i * 4 + 0] * inv, O[i * 4 + 1] * inv,
                                              O[i * 4 + 2] * inv, O[i * 4 + 3] * inv);
    }
    __syncthreads();
    if (wid == 0) TCGEN05_DEALLOC(tmem, 256);
#endif
}

// ---------------------------------------------------------------------------
// Launch sequence
// ---------------------------------------------------------------------------
extern "C" void kernel_launch(void* const* d_in, const int* in_sizes, int n_in,
                              void* d_out, int out_size)
{
    (void)in_sizes; (void)n_in; (void)out_size;
    const float* x     = (const float*)d_in[0];
    const float* w_qkv = (const float*)d_in[2];
    const float* b_qkv = (const float*)d_in[3];
    const float* w_out = (const float*)d_in[4];
    const float* b_out = (const float*)d_in[5];
    float* out = (float*)d_out;

    cudaFuncSetAttribute(mma_gemm_kernel<0>,
        cudaFuncAttributeMaxDynamicSharedMemorySize, GEMM_SMEM);
    cudaFuncSetAttribute(mma_gemm_kernel<1>,
        cudaFuncAttributeMaxDynamicSharedMemorySize, GEMM_SMEM);
    cudaFuncSetAttribute(flash_tc_kernel,
        cudaFuncAttributeMaxDynamicSharedMemorySize, FL_SMEM);

    // 1) Split fp32 operands into bf16 hi/lo
    split_kernel<0><<<8388608  / 1024, 256>>>(x,     8388608);
    split_kernel<1><<<12582912 / 1024, 256>>>(w_qkv, 12582912);
    split_kernel<2><<<4194304  / 1024, 256>>>(w_out, 4194304);

    // 2) QKV projection (tcgen05 bf16x3, cp.async pipelined)
    {
        dim3 grid(6144 / GBN, 4096 / GBM);
        mma_gemm_kernel<0><<<grid, 256, GEMM_SMEM>>>(b_qkv, nullptr, 2048, 6144);
    }

    // 3) Causal flash attention (tcgen05 bf16x3)
    {
        dim3 grid(SS / 128, BB * NHH);
        flash_tc_kernel<<<grid, 256, FL_SMEM>>>();
    }

    // 4) Split ctx, output projection
    split_kernel<3><<<8388608 / 1024, 256>>>(nullptr, 8388608);
    {
        dim3 grid(2048 / GBN, 4096 / GBM);
        mma_gemm_kernel<1><<<grid, 256, GEMM_SMEM>>>(b_out, out, 2048, 2048);
    }
}